// round 4
// baseline (speedup 1.0000x reference)
#include <cuda_runtime.h>
#include <cuda_bf16.h>

#define T_DIM 1024
#define B_DIM 64
#define H_DIM 1024
#define NSPLIT 16            // o-splits in k1
#define OCHUNK (H_DIM / NSPLIT)   // 64 o-values per split

// Scratch (allocation-free rule: __device__ globals)
__device__ float g_partial[NSPLIT * B_DIM * H_DIM];  // 4 MB: [s][b][h]
__device__ float g_v[B_DIM * H_DIM];                 // 256 KB
__device__ float g_energies[B_DIM * T_DIM];          // 256 KB: [b][t]

// ---------------------------------------------------------------------------
// k1: partial[s][b][h] = sum_{o in s-range} hid[b][o] * W[o][h]
// grid (H/256 h-tiles, NSPLIT, B/32), 256 threads. W read exactly once.
// ---------------------------------------------------------------------------
__global__ void __launch_bounds__(256) k1_proj_partial(
    const float* __restrict__ hid, const float* __restrict__ W)
{
    const int h  = blockIdx.x * 256 + threadIdx.x;
    const int o0 = blockIdx.y * OCHUNK;
    const int b0 = blockIdx.z * 32;

    __shared__ float sh[32 * OCHUNK];  // sh[bb][oo], 8 KB
    for (int i = threadIdx.x; i < 32 * OCHUNK; i += 256) {
        int bb = i / OCHUNK;
        int oo = i % OCHUNK;
        sh[i] = hid[(b0 + bb) * H_DIM + o0 + oo];
    }
    __syncthreads();

    float w[OCHUNK];
#pragma unroll
    for (int oo = 0; oo < OCHUNK; oo++)
        w[oo] = W[(o0 + oo) * H_DIM + h];

    float* part = g_partial + blockIdx.y * (B_DIM * H_DIM) + h;

#pragma unroll 4
    for (int bb = 0; bb < 32; bb++) {
        const float4* s4 = reinterpret_cast<const float4*>(sh + bb * OCHUNK);
        float acc = 0.f;
#pragma unroll
        for (int q = 0; q < OCHUNK / 4; q++) {
            float4 x = s4[q];
            acc += x.x * w[4 * q + 0] + x.y * w[4 * q + 1]
                 + x.z * w[4 * q + 2] + x.w * w[4 * q + 3];
        }
        part[(b0 + bb) * H_DIM] = acc;
    }
}

// ---------------------------------------------------------------------------
// k1b: v[i] = sum_s partial[s][i]   (deterministic reduction, no atomics)
// ---------------------------------------------------------------------------
__global__ void __launch_bounds__(256) k1b_reduce()
{
    int i = blockIdx.x * 256 + threadIdx.x;  // 65536 total
    float s = 0.f;
#pragma unroll
    for (int p = 0; p < NSPLIT; p++)
        s += g_partial[p * (B_DIM * H_DIM) + i];
    g_v[i] = s;
}

// ---------------------------------------------------------------------------
// k2: energies[b][t] = <enc[t,b,:], v[b,:]>
// Block = (b, 128-row t-chunk). v[b] in SMEM (4 KB). Each of 8 warps owns
// 16 rows, processed 2 at a time (2 indep acc chains -> 16 LDG.128 in
// flight). Low regs + launch_bounds(256,2) -> >=16 warps/SM for MLP.
// ---------------------------------------------------------------------------
__global__ void __launch_bounds__(256, 2) k2_energies(const float* __restrict__ enc)
{
    __shared__ float4 sv[H_DIM / 4];   // 4 KB: v[b] as float4
    const int b = blockIdx.x;

    sv[threadIdx.x] = reinterpret_cast<const float4*>(g_v + b * H_DIM)[threadIdx.x];
    __syncthreads();

    const int warp = threadIdx.x >> 5;
    const int lane = threadIdx.x & 31;
    const int t0   = blockIdx.y * 128 + warp * 16;

    const size_t row_stride4 = (size_t)B_DIM * H_DIM / 4;   // float4 units
    const float4* e4 = reinterpret_cast<const float4*>(
        enc + ((size_t)t0 * B_DIM + b) * H_DIM) + lane;

    float* eout = g_energies + b * T_DIM + t0;

    for (int i = 0; i < 16; i += 2) {
        float acc0 = 0.f, acc1 = 0.f;
#pragma unroll
        for (int k = 0; k < 8; k++) {
            float4 x0 = e4[32 * k];
            float4 x1 = e4[row_stride4 + 32 * k];
            float4 vv = sv[lane + 32 * k];
            acc0 += x0.x * vv.x + x0.y * vv.y + x0.z * vv.z + x0.w * vv.w;
            acc1 += x1.x * vv.x + x1.y * vv.y + x1.z * vv.z + x1.w * vv.w;
        }
#pragma unroll
        for (int off = 16; off; off >>= 1) {
            acc0 += __shfl_xor_sync(0xffffffffu, acc0, off);
            acc1 += __shfl_xor_sync(0xffffffffu, acc1, off);
        }
        if (lane == 0) {
            eout[i]     = acc0;
            eout[i + 1] = acc1;
        }
        e4 += 2 * row_stride4;
    }
}

// ---------------------------------------------------------------------------
// k3: softmax over T per row b — one warp per row, one block per row so the
// 64 rows spread over 64 SMs. All-shuffle reductions, float4 I/O.
// Bias dropped (softmax shift invariance).
// ---------------------------------------------------------------------------
__global__ void __launch_bounds__(32) k3_softmax(float* __restrict__ out)
{
    const int lane = threadIdx.x;
    const int b    = blockIdx.x;

    const float4* e4 = reinterpret_cast<const float4*>(g_energies + b * T_DIM);
    float4 vals[8];
#pragma unroll
    for (int k = 0; k < 8; k++)
        vals[k] = e4[lane + 32 * k];

    float m = -1e30f;
#pragma unroll
    for (int k = 0; k < 8; k++)
        m = fmaxf(m, fmaxf(fmaxf(vals[k].x, vals[k].y), fmaxf(vals[k].z, vals[k].w)));
#pragma unroll
    for (int off = 16; off; off >>= 1)
        m = fmaxf(m, __shfl_xor_sync(0xffffffffu, m, off));

    float lsum = 0.f;
#pragma unroll
    for (int k = 0; k < 8; k++) {
        vals[k].x = __expf(vals[k].x - m);
        vals[k].y = __expf(vals[k].y - m);
        vals[k].z = __expf(vals[k].z - m);
        vals[k].w = __expf(vals[k].w - m);
        lsum += vals[k].x + vals[k].y + vals[k].z + vals[k].w;
    }
#pragma unroll
    for (int off = 16; off; off >>= 1)
        lsum += __shfl_xor_sync(0xffffffffu, lsum, off);
    const float inv = 1.f / lsum;

    float4* o4 = reinterpret_cast<float4*>(out + b * T_DIM);
#pragma unroll
    for (int k = 0; k < 8; k++) {
        float4 r = vals[k];
        r.x *= inv; r.y *= inv; r.z *= inv; r.w *= inv;
        o4[lane + 32 * k] = r;
    }
}

// ---------------------------------------------------------------------------
extern "C" void kernel_launch(void* const* d_in, const int* in_sizes, int n_in,
                              void* d_out, int out_size)
{
    const float* hid = (const float*)d_in[0];   // [1, B, H]
    const float* enc = (const float*)d_in[1];   // [T, B, H]
    const float* W   = (const float*)d_in[2];   // [H, H]
    // d_in[3] = bias: dropped — softmax shift-invariance makes it a no-op.
    float* out = (float*)d_out;                 // [B, 1, T]

    k1_proj_partial<<<dim3(H_DIM / 256, NSPLIT, 2), 256>>>(hid, W);
    k1b_reduce<<<(B_DIM * H_DIM) / 256, 256>>>();
    k2_energies<<<dim3(B_DIM, T_DIM / 128), 256>>>(enc);
    k3_softmax<<<B_DIM, 32>>>(out);
}